// round 5
// baseline (speedup 1.0000x reference)
#include <cuda_runtime.h>
#include <cuda_bf16.h>
#include <math.h>
#include <stdint.h>

#define N_NODES 12000
#define N_EDGES 384000
#define FIN_    128
#define DD      64
#define BUF     (N_NODES * DD)   // 768000

// Scratch (no allocation allowed)
__device__ float  g_fsc[6 * BUF + N_NODES];
__device__ int    g_isc[N_NODES + (N_NODES + 1) + N_NODES + N_EDGES];
__device__ double g_sums[384];   // 3 layers x (64 sum + 64 sumsq)

// ---------------- graph prep ----------------
__global__ void zero_all_kernel(int* cnt, double* sums) {
    int i = blockIdx.x * 256 + threadIdx.x;
    if (i < N_NODES) cnt[i] = 0;
    if (i < 384) sums[i] = 0.0;
}

__global__ void hist_kernel(const int* __restrict__ dst, int* cnt) {
    int i = blockIdx.x * 256 + threadIdx.x;
    atomicAdd(&cnt[dst[i]], 1);
}

__global__ void scan_kernel(const int* __restrict__ cnt, int* __restrict__ off,
                            int* __restrict__ cur, float* __restrict__ dis) {
    __shared__ int part[1024];
    const int C = 12;
    int tid = threadIdx.x;
    int base = tid * C;
    int loc[C];
    int s = 0;
#pragma unroll
    for (int j = 0; j < C; j++) {
        int i = base + j;
        int v = (i < N_NODES) ? cnt[i] : 0;
        loc[j] = v; s += v;
    }
    part[tid] = s;
    __syncthreads();
    for (int d = 1; d < 1024; d <<= 1) {
        int v = 0;
        if (tid >= d) v = part[tid - d];
        __syncthreads();
        part[tid] += v;
        __syncthreads();
    }
    int run = (tid == 0) ? 0 : part[tid - 1];
#pragma unroll
    for (int j = 0; j < C; j++) {
        int i = base + j;
        if (i < N_NODES) {
            off[i] = run; cur[i] = run;
            dis[i] = rsqrtf((float)(loc[j] + 1));
            run += loc[j];
        }
    }
    if (tid == 1023) off[N_NODES] = run;
}

__global__ void fill_kernel(const int* __restrict__ src, const int* __restrict__ dst,
                            int* cur, int* __restrict__ csr) {
    int i = blockIdx.x * 256 + threadIdx.x;
    int p = atomicAdd(&cur[dst[i]], 1);
    csr[p] = src[i];
}

// -------- GCN gemm: Y[row] = dis[row] * ( bnfold(X) @ W ) , NOUT=64 ---------
// FOLD: X is pre-BN sigmoid output; fold BN per-column affine into the GEMM:
//   bn(S)@W = (S .* a) @ W + sum_k d[k] W[k,:],  a = inv*gamma, d = beta - mu*inv*gamma
template <int FIN, bool FOLD>
__global__ void gcn_gemm_kernel(const float* __restrict__ X, const float* __restrict__ W,
                                const float* __restrict__ dis, const double* __restrict__ sums,
                                const float* __restrict__ gamma, const float* __restrict__ beta,
                                float* __restrict__ Y) {
    __shared__ float xs[16 * FIN];
    __shared__ float afold[FIN], dfold[FIN];
    int tid = threadIdx.x;
    int rowbase = blockIdx.x * 16;
    if (FOLD) {
        if (tid < FIN) {
            double mu  = sums[tid] * (1.0 / N_NODES);
            double var = sums[FIN + tid] * (1.0 / N_NODES) - mu * mu;
            float a = rsqrtf((float)var + 1e-4f) * gamma[tid];
            afold[tid] = a;
            dfold[tid] = beta[tid] - (float)mu * a;
        }
        __syncthreads();
    }
    const float4* Xg = (const float4*)(X + (size_t)rowbase * FIN);
    float4* xs4 = (float4*)xs;
    for (int u = tid; u < 16 * FIN / 4; u += 256) {
        float4 v = Xg[u];
        if (FOLD) {
            int k = (u & (FIN / 4 - 1)) * 4;
            v.x *= afold[k]; v.y *= afold[k + 1]; v.z *= afold[k + 2]; v.w *= afold[k + 3];
        }
        xs4[u] = v;
    }
    __syncthreads();

    int col = tid & 63;
    int rl  = tid >> 6;                 // 4 rows per thread
    float acc[4] = {0.f, 0.f, 0.f, 0.f};
    float bacc = 0.f;
#pragma unroll 4
    for (int k = 0; k < FIN; k++) {
        float w = __ldg(&W[k * 64 + col]);
#pragma unroll
        for (int r = 0; r < 4; r++)
            acc[r] += xs[(rl * 4 + r) * FIN + k] * w;
        if (FOLD) bacc += dfold[k] * w;
    }
#pragma unroll
    for (int r = 0; r < 4; r++) {
        int row = rowbase + rl * 4 + r;
        float v = acc[r];
        if (FOLD) v += bacc;
        Y[(size_t)row * 64 + col] = v * dis[row];
    }
}

// ---- gather + bias + sigmoid + fused BN stats (one warp per node) ----------
__global__ void gather_sig_stats_kernel(const float* __restrict__ hs, const float* __restrict__ dis,
                                        const int* __restrict__ off, const int* __restrict__ csr,
                                        const float* __restrict__ bias,
                                        float* __restrict__ sbuf, double* __restrict__ sums) {
    __shared__ double sh[128];
    int tid = threadIdx.x;
    if (tid < 128) sh[tid] = 0.0;
    __syncthreads();

    int warp = (blockIdx.x * 256 + tid) >> 5;
    int lane = tid & 31;
    const float2* h2 = (const float2*)hs;
    float2 acc = h2[(size_t)warp * 32 + lane];
    int e0 = off[warp], e1 = off[warp + 1];
    for (int e = e0; e < e1; e++) {
        int s = __ldg(&csr[e]);
        float2 v = h2[(size_t)s * 32 + lane];
        acc.x += v.x; acc.y += v.y;
    }
    float dd = dis[warp];
    float2 bb = ((const float2*)bias)[lane];
    float vx = __fdividef(1.f, 1.f + __expf(-(dd * acc.x + bb.x)));
    float vy = __fdividef(1.f, 1.f + __expf(-(dd * acc.y + bb.y)));
    ((float2*)sbuf)[(size_t)warp * 32 + lane] = make_float2(vx, vy);

    int c = lane * 2;
    atomicAdd(&sh[c],          (double)vx);
    atomicAdd(&sh[c + 1],      (double)vy);
    atomicAdd(&sh[64 + c],     (double)vx * (double)vx);
    atomicAdd(&sh[64 + c + 1], (double)vy * (double)vy);
    __syncthreads();
    if (tid < 128) atomicAdd(&sums[tid], sh[tid]);
}

// ------- z = noise * exp(bn(SBs)) + bn(SBm)  (BN of both layers fused) ------
__global__ void z_bn_kernel(const float* __restrict__ noise,
                            const float* __restrict__ SBm, const float* __restrict__ SBs,
                            const double* __restrict__ sums,
                            const float* __restrict__ gm, const float* __restrict__ bem,
                            const float* __restrict__ gs, const float* __restrict__ bes,
                            float* __restrict__ z) {
    int idx = blockIdx.x * 256 + threadIdx.x;
    int c = idx & 63;
    const double INVN = 1.0 / N_NODES;
    double mum = sums[128 + c] * INVN;
    double varm = sums[128 + 64 + c] * INVN - mum * mum;
    float am = rsqrtf((float)varm + 1e-4f) * gm[c];
    float zm = (float)((double)SBm[idx] - mum) * am + bem[c];
    double mus = sums[256 + c] * INVN;
    double vars = sums[256 + 64 + c] * INVN - mus * mus;
    float as = rsqrtf((float)vars + 1e-4f) * gs[c];
    float zs = (float)((double)SBs[idx] - mus) * as + bes[c];
    z[idx] = noise[idx] * expf(zs) + zm;
}

// --------- decoder: out = leaky(Z@Dw1+Db1) @ Dw2 + Db2 (fused) --------------
__global__ void decoder_kernel(const float* __restrict__ Z,
                               const float* __restrict__ Dw1, const float* __restrict__ Db1,
                               const float* __restrict__ Dw2, const float* __restrict__ Db2,
                               float* __restrict__ out) {
    __shared__ float zs[16 * 64];
    __shared__ float h1s[16 * 64];
    int tid = threadIdx.x;
    int rowbase = blockIdx.x * 16;
    const float4* Zg = (const float4*)(Z + (size_t)rowbase * 64);
    float4* zs4 = (float4*)zs;
    if (tid < 256) zs4[tid] = Zg[tid];
    __syncthreads();
    {
        int col = tid & 63, r4 = tid >> 6;
#pragma unroll
        for (int r = 0; r < 4; r++) {
            int row = r4 * 4 + r;
            float acc = Db1[col];
#pragma unroll 8
            for (int k = 0; k < 64; k++) acc += zs[row * 64 + k] * __ldg(&Dw1[k * 64 + col]);
            h1s[row * 64 + col] = (acc > 0.f) ? acc : 0.01f * acc;
        }
    }
    __syncthreads();
    {
        int col = tid & 127, r2 = tid >> 7;
#pragma unroll
        for (int r = 0; r < 8; r++) {
            int row = r2 * 8 + r;
            float acc = Db2[col];
#pragma unroll 8
            for (int k = 0; k < 64; k++) acc += h1s[row * 64 + k] * __ldg(&Dw2[k * 128 + col]);
            out[(size_t)(rowbase + row) * 128 + col] = acc;
        }
    }
}

// ====== A_pred = sigmoid(z z^T): HMMA bf16 split, SYMMETRIC (upper-tri) =====
#define TPITCH 72   // bf16 elements per smem row (144 bytes)

__device__ __forceinline__ void mma_bf16(float* c, const uint32_t* a, const uint32_t* b) {
    asm volatile(
        "mma.sync.aligned.m16n8k16.row.col.f32.bf16.bf16.f32 "
        "{%0,%1,%2,%3}, {%4,%5,%6,%7}, {%8,%9}, {%0,%1,%2,%3};"
        : "+f"(c[0]), "+f"(c[1]), "+f"(c[2]), "+f"(c[3])
        : "r"(a[0]), "r"(a[1]), "r"(a[2]), "r"(a[3]), "r"(b[0]), "r"(b[1]));
}

__global__ void __launch_bounds__(256, 2)
apred_mma_kernel(const float* __restrict__ z, float* __restrict__ out) {
    int bi = blockIdx.y, bj = blockIdx.x;
    if (bj < bi) return;                        // symmetric: upper triangle only

    extern __shared__ __nv_bfloat16 sm[];
    __nv_bfloat16* Ahi = sm;
    __nv_bfloat16* Alo = sm + 128 * TPITCH;
    __nv_bfloat16* Bhi = sm + 2 * 128 * TPITCH;
    __nv_bfloat16* Blo = sm + 3 * 128 * TPITCH;

    int tid = threadIdx.x;
    int row0 = bi * 128, col0 = bj * 128;

    for (int u = tid; u < 2048; u += 256) {
        int r = u >> 4, f4 = u & 15;
        int gr = row0 + r;
        float4 v = make_float4(0.f, 0.f, 0.f, 0.f);
        if (gr < N_NODES) v = *(const float4*)(z + (size_t)gr * 64 + f4 * 4);
        {
            __nv_bfloat16 h0 = __float2bfloat16_rn(v.x), h1 = __float2bfloat16_rn(v.y);
            __nv_bfloat16 h2 = __float2bfloat16_rn(v.z), h3 = __float2bfloat16_rn(v.w);
            __nv_bfloat16 l0 = __float2bfloat16_rn(v.x - __bfloat162float(h0));
            __nv_bfloat16 l1 = __float2bfloat16_rn(v.y - __bfloat162float(h1));
            __nv_bfloat16 l2 = __float2bfloat16_rn(v.z - __bfloat162float(h2));
            __nv_bfloat16 l3 = __float2bfloat16_rn(v.w - __bfloat162float(h3));
            int e = r * TPITCH + f4 * 4;
            *(uint32_t*)&Ahi[e]     = ((uint32_t)__bfloat16_as_ushort(h1) << 16) | __bfloat16_as_ushort(h0);
            *(uint32_t*)&Ahi[e + 2] = ((uint32_t)__bfloat16_as_ushort(h3) << 16) | __bfloat16_as_ushort(h2);
            *(uint32_t*)&Alo[e]     = ((uint32_t)__bfloat16_as_ushort(l1) << 16) | __bfloat16_as_ushort(l0);
            *(uint32_t*)&Alo[e + 2] = ((uint32_t)__bfloat16_as_ushort(l3) << 16) | __bfloat16_as_ushort(l2);
        }
        int gc = col0 + r;
        float4 w = make_float4(0.f, 0.f, 0.f, 0.f);
        if (gc < N_NODES) w = *(const float4*)(z + (size_t)gc * 64 + f4 * 4);
        {
            __nv_bfloat16 h0 = __float2bfloat16_rn(w.x), h1 = __float2bfloat16_rn(w.y);
            __nv_bfloat16 h2 = __float2bfloat16_rn(w.z), h3 = __float2bfloat16_rn(w.w);
            __nv_bfloat16 l0 = __float2bfloat16_rn(w.x - __bfloat162float(h0));
            __nv_bfloat16 l1 = __float2bfloat16_rn(w.y - __bfloat162float(h1));
            __nv_bfloat16 l2 = __float2bfloat16_rn(w.z - __bfloat162float(h2));
            __nv_bfloat16 l3 = __float2bfloat16_rn(w.w - __bfloat162float(h3));
            int e = r * TPITCH + f4 * 4;
            *(uint32_t*)&Bhi[e]     = ((uint32_t)__bfloat16_as_ushort(h1) << 16) | __bfloat16_as_ushort(h0);
            *(uint32_t*)&Bhi[e + 2] = ((uint32_t)__bfloat16_as_ushort(h3) << 16) | __bfloat16_as_ushort(h2);
            *(uint32_t*)&Blo[e]     = ((uint32_t)__bfloat16_as_ushort(l1) << 16) | __bfloat16_as_ushort(l0);
            *(uint32_t*)&Blo[e + 2] = ((uint32_t)__bfloat16_as_ushort(l3) << 16) | __bfloat16_as_ushort(l2);
        }
    }
    __syncthreads();

    int wid = tid >> 5, lane = tid & 31;
    int gid = lane >> 2, tig = lane & 3;
    int m0 = (wid & 3) * 32;
    int n0 = (wid >> 2) * 64;

    float acc[2][8][4];
#pragma unroll
    for (int h = 0; h < 2; h++)
#pragma unroll
        for (int nb = 0; nb < 8; nb++)
#pragma unroll
            for (int q = 0; q < 4; q++) acc[h][nb][q] = 0.f;

#pragma unroll
    for (int p = 0; p < 3; p++) {
        const __nv_bfloat16* Ap = (p == 2) ? Alo : Ahi;
        const __nv_bfloat16* Bp = (p == 1) ? Blo : Bhi;
#pragma unroll
        for (int ks = 0; ks < 4; ks++) {
            int k0 = ks * 16;
            uint32_t a[2][4];
#pragma unroll
            for (int h = 0; h < 2; h++) {
                int r = m0 + 16 * h + gid;
                int e = r * TPITCH + k0 + 2 * tig;
                a[h][0] = *(const uint32_t*)&Ap[e];
                a[h][1] = *(const uint32_t*)&Ap[e + 8 * TPITCH];
                a[h][2] = *(const uint32_t*)&Ap[e + 8];
                a[h][3] = *(const uint32_t*)&Ap[e + 8 * TPITCH + 8];
            }
#pragma unroll
            for (int nb = 0; nb < 8; nb++) {
                int nr = n0 + 8 * nb + gid;
                int e = nr * TPITCH + k0 + 2 * tig;
                uint32_t b[2];
                b[0] = *(const uint32_t*)&Bp[e];
                b[1] = *(const uint32_t*)&Bp[e + 8];
                mma_bf16(acc[0][nb], a[0], b);
                mma_bf16(acc[1][nb], a[1], b);
            }
        }
    }

    // sigmoid once, in registers
#pragma unroll
    for (int h = 0; h < 2; h++)
#pragma unroll
        for (int nb = 0; nb < 8; nb++)
#pragma unroll
            for (int q = 0; q < 4; q++)
                acc[h][nb][q] = __fdividef(1.f, 1.f + __expf(-acc[h][nb][q]));

    // direct tile store: float2 per quad-lane (32B sectors, coalesced)
#pragma unroll
    for (int h = 0; h < 2; h++) {
#pragma unroll
        for (int nb = 0; nb < 8; nb++) {
            float* q = acc[h][nb];
            int r0 = row0 + m0 + 16 * h + gid;
            int c  = col0 + n0 + 8 * nb + 2 * tig;
            if (c < N_NODES) {
                if (r0 < N_NODES)
                    *(float2*)(out + (size_t)r0 * N_NODES + c) = make_float2(q[0], q[1]);
                int r1 = r0 + 8;
                if (r1 < N_NODES)
                    *(float2*)(out + (size_t)r1 * N_NODES + c) = make_float2(q[2], q[3]);
            }
        }
    }

    // mirror store (off-diagonal): out[c][r] = out[r][c]. Lanes sharing tig
    // cover 8 consecutive r -> each STG.32 group forms exact 32B sectors.
    // bi < bj here implies bi <= 92, so r0, r0+8 < 11904+128 <= N always.
    if (bi != bj) {
#pragma unroll
        for (int h = 0; h < 2; h++) {
#pragma unroll
            for (int nb = 0; nb < 8; nb++) {
                float* q = acc[h][nb];
                int r0 = row0 + m0 + 16 * h + gid;
                int c  = col0 + n0 + 8 * nb + 2 * tig;
                if (c < N_NODES) {
                    out[(size_t)c * N_NODES + r0]     = q[0];
                    out[(size_t)c * N_NODES + r0 + 8] = q[2];
                }
                if (c + 1 < N_NODES) {
                    out[(size_t)(c + 1) * N_NODES + r0]     = q[1];
                    out[(size_t)(c + 1) * N_NODES + r0 + 8] = q[3];
                }
            }
        }
    }
}

// ---------------- launch -----------------------------------------------------
extern "C" void kernel_launch(void* const* d_in, const int* in_sizes, int n_in,
                              void* d_out, int out_size) {
    const float* x     = (const float*)d_in[0];
    const int*   src   = (const int*)  d_in[1];
    const int*   dst   = (const int*)  d_in[2];
    const float* noise = (const float*)d_in[4];
    const float* W0  = (const float*)d_in[5];
    const float* b0  = (const float*)d_in[6];
    const float* g0  = (const float*)d_in[7];
    const float* be0 = (const float*)d_in[8];
    const float* Wm  = (const float*)d_in[9];
    const float* bm  = (const float*)d_in[10];
    const float* gm  = (const float*)d_in[11];
    const float* bem = (const float*)d_in[12];
    const float* Ws  = (const float*)d_in[13];
    const float* bs  = (const float*)d_in[14];
    const float* gs  = (const float*)d_in[15];
    const float* bes = (const float*)d_in[16];
    const float* Dw1 = (const float*)d_in[17];
    const float* Db1 = (const float*)d_in[18];
    const float* Dw2 = (const float*)d_in[19];
    const float* Db2 = (const float*)d_in[20];
    float* out = (float*)d_out;

    float* fsc; int* isc; double* sums;
    cudaGetSymbolAddress((void**)&fsc, g_fsc);
    cudaGetSymbolAddress((void**)&isc, g_isc);
    cudaGetSymbolAddress((void**)&sums, g_sums);

    float* HS  = fsc + 0 * BUF;
    float* SB1 = fsc + 1 * BUF;
    float* SB2 = fsc + 2 * BUF;
    float* SB3 = fsc + 3 * BUF;
    float* Z   = fsc + 4 * BUF;
    float* DIS = fsc + 5 * BUF;
    int* CNT = isc;
    int* OFF = CNT + N_NODES;
    int* CUR = OFF + N_NODES + 1;
    int* CSR = CUR + N_NODES;

    const int APRED_SMEM = 4 * 128 * TPITCH * 2;   // 73728 bytes
    cudaFuncSetAttribute(apred_mma_kernel, cudaFuncAttributeMaxDynamicSharedMemorySize, APRED_SMEM);

    // graph prep
    zero_all_kernel<<<47, 256>>>(CNT, sums);
    hist_kernel<<<1500, 256>>>(dst, CNT);
    scan_kernel<<<1, 1024>>>(CNT, OFF, CUR, DIS);
    fill_kernel<<<1500, 256>>>(src, dst, CUR, CSR);

    // layer 1: x(128) -> SB1  (stats for BN1 fused into gather)
    gcn_gemm_kernel<FIN_, false><<<750, 256>>>(x, W0, DIS, sums, nullptr, nullptr, HS);
    gather_sig_stats_kernel<<<1500, 256>>>(HS, DIS, OFF, CSR, b0, SB1, sums);

    // layer 2 (mean): BN1 folded into gemm
    gcn_gemm_kernel<DD, true><<<750, 256>>>(SB1, Wm, DIS, sums, g0, be0, HS);
    gather_sig_stats_kernel<<<1500, 256>>>(HS, DIS, OFF, CSR, bm, SB2, sums + 128);

    // layer 3 (logstd): BN1 folded into gemm
    gcn_gemm_kernel<DD, true><<<750, 256>>>(SB1, Ws, DIS, sums, g0, be0, HS);
    gather_sig_stats_kernel<<<1500, 256>>>(HS, DIS, OFF, CSR, bs, SB3, sums + 256);

    // z = noise*exp(bn(SB3)) + bn(SB2)
    z_bn_kernel<<<3000, 256>>>(noise, SB2, SB3, sums, gm, bem, gs, bes, Z);

    // decoder (both layers fused) -> out[0 : 12000*128]
    decoder_kernel<<<750, 256>>>(Z, Dw1, Db1, Dw2, Db2, out);

    // A_pred -> out[12000*128 : ]  (symmetric upper-tri HMMA)
    dim3 grid((N_NODES + 127) / 128, (N_NODES + 127) / 128);
    apred_mma_kernel<<<grid, 256, APRED_SMEM>>>(Z, out + (size_t)N_NODES * FIN_);
}

// round 6
// speedup vs baseline: 1.2267x; 1.2267x over previous
#include <cuda_runtime.h>
#include <cuda_bf16.h>
#include <math.h>
#include <stdint.h>

#define N_NODES 12000
#define N_EDGES 384000
#define FIN_    128
#define DD      64
#define BUF     (N_NODES * DD)   // 768000

// Scratch (no allocation allowed)
__device__ float  g_fsc[6 * BUF + N_NODES];
__device__ int    g_isc[N_NODES + (N_NODES + 1) + N_NODES + N_EDGES];
__device__ double g_sums[384];   // 3 layers x (64 sum + 64 sumsq)

// ---------------- graph prep ----------------
__global__ void zero_all_kernel(int* cnt, double* sums) {
    int i = blockIdx.x * 256 + threadIdx.x;
    if (i < N_NODES) cnt[i] = 0;
    if (i < 384) sums[i] = 0.0;
}

__global__ void hist_kernel(const int* __restrict__ dst, int* cnt) {
    int i = blockIdx.x * 256 + threadIdx.x;
    atomicAdd(&cnt[dst[i]], 1);
}

__global__ void scan_kernel(const int* __restrict__ cnt, int* __restrict__ off,
                            int* __restrict__ cur, float* __restrict__ dis) {
    __shared__ int part[1024];
    const int C = 12;
    int tid = threadIdx.x;
    int base = tid * C;
    int loc[C];
    int s = 0;
#pragma unroll
    for (int j = 0; j < C; j++) {
        int i = base + j;
        int v = (i < N_NODES) ? cnt[i] : 0;
        loc[j] = v; s += v;
    }
    part[tid] = s;
    __syncthreads();
    for (int d = 1; d < 1024; d <<= 1) {
        int v = 0;
        if (tid >= d) v = part[tid - d];
        __syncthreads();
        part[tid] += v;
        __syncthreads();
    }
    int run = (tid == 0) ? 0 : part[tid - 1];
#pragma unroll
    for (int j = 0; j < C; j++) {
        int i = base + j;
        if (i < N_NODES) {
            off[i] = run; cur[i] = run;
            dis[i] = rsqrtf((float)(loc[j] + 1));
            run += loc[j];
        }
    }
    if (tid == 1023) off[N_NODES] = run;
}

__global__ void fill_kernel(const int* __restrict__ src, const int* __restrict__ dst,
                            int* cur, int* __restrict__ csr) {
    int i = blockIdx.x * 256 + threadIdx.x;
    int p = atomicAdd(&cur[dst[i]], 1);
    csr[p] = src[i];
}

// -------- GCN gemm: Y[row] = dis[row] * ( bnfold(X) @ W ) , NOUT=64 ---------
// FOLD: X is pre-BN sigmoid output; fold BN per-column affine into the GEMM:
//   bn(S)@W = (S .* a) @ W + sum_k d[k] W[k,:],  a = inv*gamma, d = beta - mu*inv*gamma
template <int FIN, bool FOLD>
__global__ void gcn_gemm_kernel(const float* __restrict__ X, const float* __restrict__ W,
                                const float* __restrict__ dis, const double* __restrict__ sums,
                                const float* __restrict__ gamma, const float* __restrict__ beta,
                                float* __restrict__ Y) {
    __shared__ float xs[16 * FIN];
    __shared__ float afold[FIN], dfold[FIN];
    int tid = threadIdx.x;
    int rowbase = blockIdx.x * 16;
    if (FOLD) {
        if (tid < FIN) {
            double mu  = sums[tid] * (1.0 / N_NODES);
            double var = sums[FIN + tid] * (1.0 / N_NODES) - mu * mu;
            float a = rsqrtf((float)var + 1e-4f) * gamma[tid];
            afold[tid] = a;
            dfold[tid] = beta[tid] - (float)mu * a;
        }
        __syncthreads();
    }
    const float4* Xg = (const float4*)(X + (size_t)rowbase * FIN);
    float4* xs4 = (float4*)xs;
    for (int u = tid; u < 16 * FIN / 4; u += 256) {
        float4 v = Xg[u];
        if (FOLD) {
            int k = (u & (FIN / 4 - 1)) * 4;
            v.x *= afold[k]; v.y *= afold[k + 1]; v.z *= afold[k + 2]; v.w *= afold[k + 3];
        }
        xs4[u] = v;
    }
    __syncthreads();

    int col = tid & 63;
    int rl  = tid >> 6;                 // 4 rows per thread
    float acc[4] = {0.f, 0.f, 0.f, 0.f};
    float bacc = 0.f;
#pragma unroll 4
    for (int k = 0; k < FIN; k++) {
        float w = __ldg(&W[k * 64 + col]);
#pragma unroll
        for (int r = 0; r < 4; r++)
            acc[r] += xs[(rl * 4 + r) * FIN + k] * w;
        if (FOLD) bacc += dfold[k] * w;
    }
#pragma unroll
    for (int r = 0; r < 4; r++) {
        int row = rowbase + rl * 4 + r;
        float v = acc[r];
        if (FOLD) v += bacc;
        Y[(size_t)row * 64 + col] = v * dis[row];
    }
}

// ---- gather + bias + sigmoid + fused BN stats (one warp per node) ----------
// Stats path: NO smem atomics. Each warp owns one node; it stores its 64
// channel values via plain STS. Then 128 threads tree-sum the 8 warps in
// double registers and do one global f64 atomic per channel per block.
__global__ void gather_sig_stats_kernel(const float* __restrict__ hs, const float* __restrict__ dis,
                                        const int* __restrict__ off, const int* __restrict__ csr,
                                        const float* __restrict__ bias,
                                        float* __restrict__ sbuf, double* __restrict__ sums) {
    __shared__ float shv[8][64];
    int tid = threadIdx.x;
    int wlocal = tid >> 5;
    int warp = (blockIdx.x * 256 + tid) >> 5;
    int lane = tid & 31;
    const float2* h2 = (const float2*)hs;
    float2 acc = h2[(size_t)warp * 32 + lane];
    int e0 = off[warp], e1 = off[warp + 1];
    for (int e = e0; e < e1; e++) {
        int s = __ldg(&csr[e]);
        float2 v = h2[(size_t)s * 32 + lane];
        acc.x += v.x; acc.y += v.y;
    }
    float dd = dis[warp];
    float2 bb = ((const float2*)bias)[lane];
    float vx = __fdividef(1.f, 1.f + __expf(-(dd * acc.x + bb.x)));
    float vy = __fdividef(1.f, 1.f + __expf(-(dd * acc.y + bb.y)));
    ((float2*)sbuf)[(size_t)warp * 32 + lane] = make_float2(vx, vy);

    shv[wlocal][lane * 2]     = vx;
    shv[wlocal][lane * 2 + 1] = vy;
    __syncthreads();
    if (tid < 128) {
        int c = tid & 63;
        if (tid < 64) {
            double s = 0.0;
#pragma unroll
            for (int w = 0; w < 8; w++) s += (double)shv[w][c];
            atomicAdd(&sums[c], s);
        } else {
            double s2 = 0.0;
#pragma unroll
            for (int w = 0; w < 8; w++) {
                double v = (double)shv[w][c];
                s2 += v * v;
            }
            atomicAdd(&sums[64 + c], s2);
        }
    }
}

// ------- z = noise * exp(bn(SBs)) + bn(SBm)  (BN of both layers fused) ------
__global__ void z_bn_kernel(const float* __restrict__ noise,
                            const float* __restrict__ SBm, const float* __restrict__ SBs,
                            const double* __restrict__ sums,
                            const float* __restrict__ gm, const float* __restrict__ bem,
                            const float* __restrict__ gs, const float* __restrict__ bes,
                            float* __restrict__ z) {
    int idx = blockIdx.x * 256 + threadIdx.x;
    int c = idx & 63;
    const double INVN = 1.0 / N_NODES;
    double mum = sums[128 + c] * INVN;
    double varm = sums[128 + 64 + c] * INVN - mum * mum;
    float am = rsqrtf((float)varm + 1e-4f) * gm[c];
    float zm = (float)((double)SBm[idx] - mum) * am + bem[c];
    double mus = sums[256 + c] * INVN;
    double vars = sums[256 + 64 + c] * INVN - mus * mus;
    float as = rsqrtf((float)vars + 1e-4f) * gs[c];
    float zs = (float)((double)SBs[idx] - mus) * as + bes[c];
    z[idx] = noise[idx] * expf(zs) + zm;
}

// --------- decoder: out = leaky(Z@Dw1+Db1) @ Dw2 + Db2 (fused) --------------
__global__ void decoder_kernel(const float* __restrict__ Z,
                               const float* __restrict__ Dw1, const float* __restrict__ Db1,
                               const float* __restrict__ Dw2, const float* __restrict__ Db2,
                               float* __restrict__ out) {
    __shared__ float zs[16 * 64];
    __shared__ float h1s[16 * 64];
    int tid = threadIdx.x;
    int rowbase = blockIdx.x * 16;
    const float4* Zg = (const float4*)(Z + (size_t)rowbase * 64);
    float4* zs4 = (float4*)zs;
    if (tid < 256) zs4[tid] = Zg[tid];
    __syncthreads();
    {
        int col = tid & 63, r4 = tid >> 6;
#pragma unroll
        for (int r = 0; r < 4; r++) {
            int row = r4 * 4 + r;
            float acc = Db1[col];
#pragma unroll 8
            for (int k = 0; k < 64; k++) acc += zs[row * 64 + k] * __ldg(&Dw1[k * 64 + col]);
            h1s[row * 64 + col] = (acc > 0.f) ? acc : 0.01f * acc;
        }
    }
    __syncthreads();
    {
        int col = tid & 127, r2 = tid >> 7;
#pragma unroll
        for (int r = 0; r < 8; r++) {
            int row = r2 * 8 + r;
            float acc = Db2[col];
#pragma unroll 8
            for (int k = 0; k < 64; k++) acc += h1s[row * 64 + k] * __ldg(&Dw2[k * 128 + col]);
            out[(size_t)(rowbase + row) * 128 + col] = acc;
        }
    }
}

// ====== A_pred = sigmoid(z @ z^T) via mma.sync bf16 two-term split ==========
// (R4-proven configuration: full grid, direct coalesced float2 stores)
#define TPITCH 72   // bf16 elements per smem row (144 bytes)

__device__ __forceinline__ void mma_bf16(float* c, const uint32_t* a, const uint32_t* b) {
    asm volatile(
        "mma.sync.aligned.m16n8k16.row.col.f32.bf16.bf16.f32 "
        "{%0,%1,%2,%3}, {%4,%5,%6,%7}, {%8,%9}, {%0,%1,%2,%3};"
        : "+f"(c[0]), "+f"(c[1]), "+f"(c[2]), "+f"(c[3])
        : "r"(a[0]), "r"(a[1]), "r"(a[2]), "r"(a[3]), "r"(b[0]), "r"(b[1]));
}

__global__ void __launch_bounds__(256, 2)
apred_mma_kernel(const float* __restrict__ z, float* __restrict__ out) {
    extern __shared__ __nv_bfloat16 sm[];
    __nv_bfloat16* Ahi = sm;
    __nv_bfloat16* Alo = sm + 128 * TPITCH;
    __nv_bfloat16* Bhi = sm + 2 * 128 * TPITCH;
    __nv_bfloat16* Blo = sm + 3 * 128 * TPITCH;

    int tid = threadIdx.x;
    int row0 = blockIdx.y * 128, col0 = blockIdx.x * 128;

    // ---- fill: split z rows into bf16 hi/lo ----
    for (int u = tid; u < 2048; u += 256) {
        int r = u >> 4, f4 = u & 15;
        int gr = row0 + r;
        float4 v = make_float4(0.f, 0.f, 0.f, 0.f);
        if (gr < N_NODES) v = *(const float4*)(z + (size_t)gr * 64 + f4 * 4);
        {
            __nv_bfloat16 h0 = __float2bfloat16_rn(v.x), h1 = __float2bfloat16_rn(v.y);
            __nv_bfloat16 h2 = __float2bfloat16_rn(v.z), h3 = __float2bfloat16_rn(v.w);
            __nv_bfloat16 l0 = __float2bfloat16_rn(v.x - __bfloat162float(h0));
            __nv_bfloat16 l1 = __float2bfloat16_rn(v.y - __bfloat162float(h1));
            __nv_bfloat16 l2 = __float2bfloat16_rn(v.z - __bfloat162float(h2));
            __nv_bfloat16 l3 = __float2bfloat16_rn(v.w - __bfloat162float(h3));
            int e = r * TPITCH + f4 * 4;
            *(uint32_t*)&Ahi[e]     = ((uint32_t)__bfloat16_as_ushort(h1) << 16) | __bfloat16_as_ushort(h0);
            *(uint32_t*)&Ahi[e + 2] = ((uint32_t)__bfloat16_as_ushort(h3) << 16) | __bfloat16_as_ushort(h2);
            *(uint32_t*)&Alo[e]     = ((uint32_t)__bfloat16_as_ushort(l1) << 16) | __bfloat16_as_ushort(l0);
            *(uint32_t*)&Alo[e + 2] = ((uint32_t)__bfloat16_as_ushort(l3) << 16) | __bfloat16_as_ushort(l2);
        }
        int gc = col0 + r;
        float4 w = make_float4(0.f, 0.f, 0.f, 0.f);
        if (gc < N_NODES) w = *(const float4*)(z + (size_t)gc * 64 + f4 * 4);
        {
            __nv_bfloat16 h0 = __float2bfloat16_rn(w.x), h1 = __float2bfloat16_rn(w.y);
            __nv_bfloat16 h2 = __float2bfloat16_rn(w.z), h3 = __float2bfloat16_rn(w.w);
            __nv_bfloat16 l0 = __float2bfloat16_rn(w.x - __bfloat162float(h0));
            __nv_bfloat16 l1 = __float2bfloat16_rn(w.y - __bfloat162float(h1));
            __nv_bfloat16 l2 = __float2bfloat16_rn(w.z - __bfloat162float(h2));
            __nv_bfloat16 l3 = __float2bfloat16_rn(w.w - __bfloat162float(h3));
            int e = r * TPITCH + f4 * 4;
            *(uint32_t*)&Bhi[e]     = ((uint32_t)__bfloat16_as_ushort(h1) << 16) | __bfloat16_as_ushort(h0);
            *(uint32_t*)&Bhi[e + 2] = ((uint32_t)__bfloat16_as_ushort(h3) << 16) | __bfloat16_as_ushort(h2);
            *(uint32_t*)&Blo[e]     = ((uint32_t)__bfloat16_as_ushort(l1) << 16) | __bfloat16_as_ushort(l0);
            *(uint32_t*)&Blo[e + 2] = ((uint32_t)__bfloat16_as_ushort(l3) << 16) | __bfloat16_as_ushort(l2);
        }
    }
    __syncthreads();

    int wid = tid >> 5, lane = tid & 31;
    int gid = lane >> 2, tig = lane & 3;
    int m0 = (wid & 3) * 32;
    int n0 = (wid >> 2) * 64;

    float acc[2][8][4];
#pragma unroll
    for (int h = 0; h < 2; h++)
#pragma unroll
        for (int nb = 0; nb < 8; nb++)
#pragma unroll
            for (int q = 0; q < 4; q++) acc[h][nb][q] = 0.f;

#pragma unroll
    for (int p = 0; p < 3; p++) {
        const __nv_bfloat16* Ap = (p == 2) ? Alo : Ahi;
        const __nv_bfloat16* Bp = (p == 1) ? Blo : Bhi;
#pragma unroll
        for (int ks = 0; ks < 4; ks++) {
            int k0 = ks * 16;
            uint32_t a[2][4];
#pragma unroll
            for (int h = 0; h < 2; h++) {
                int r = m0 + 16 * h + gid;
                int e = r * TPITCH + k0 + 2 * tig;
                a[h][0] = *(const uint32_t*)&Ap[e];
                a[h][1] = *(const uint32_t*)&Ap[e + 8 * TPITCH];
                a[h][2] = *(const uint32_t*)&Ap[e + 8];
                a[h][3] = *(const uint32_t*)&Ap[e + 8 * TPITCH + 8];
            }
#pragma unroll
            for (int nb = 0; nb < 8; nb++) {
                int nr = n0 + 8 * nb + gid;
                int e = nr * TPITCH + k0 + 2 * tig;
                uint32_t b[2];
                b[0] = *(const uint32_t*)&Bp[e];
                b[1] = *(const uint32_t*)&Bp[e + 8];
                mma_bf16(acc[0][nb], a[0], b);
                mma_bf16(acc[1][nb], a[1], b);
            }
        }
    }

    // ---- epilogue: sigmoid + guarded float2 stores (32B per quad) ----
#pragma unroll
    for (int h = 0; h < 2; h++) {
#pragma unroll
        for (int nb = 0; nb < 8; nb++) {
            float* q = acc[h][nb];
            int r0 = row0 + m0 + 16 * h + gid;
            int c  = col0 + n0 + 8 * nb + 2 * tig;
            if (c < N_NODES) {
                if (r0 < N_NODES) {
                    float2 v;
                    v.x = __fdividef(1.f, 1.f + __expf(-q[0]));
                    v.y = __fdividef(1.f, 1.f + __expf(-q[1]));
                    *(float2*)(out + (size_t)r0 * N_NODES + c) = v;
                }
                int r1 = r0 + 8;
                if (r1 < N_NODES) {
                    float2 v;
                    v.x = __fdividef(1.f, 1.f + __expf(-q[2]));
                    v.y = __fdividef(1.f, 1.f + __expf(-q[3]));
                    *(float2*)(out + (size_t)r1 * N_NODES + c) = v;
                }
            }
        }
    }
}

// ---------------- launch -----------------------------------------------------
extern "C" void kernel_launch(void* const* d_in, const int* in_sizes, int n_in,
                              void* d_out, int out_size) {
    const float* x     = (const float*)d_in[0];
    const int*   src   = (const int*)  d_in[1];
    const int*   dst   = (const int*)  d_in[2];
    const float* noise = (const float*)d_in[4];
    const float* W0  = (const float*)d_in[5];
    const float* b0  = (const float*)d_in[6];
    const float* g0  = (const float*)d_in[7];
    const float* be0 = (const float*)d_in[8];
    const float* Wm  = (const float*)d_in[9];
    const float* bm  = (const float*)d_in[10];
    const float* gm  = (const float*)d_in[11];
    const float* bem = (const float*)d_in[12];
    const float* Ws  = (const float*)d_in[13];
    const float* bs  = (const float*)d_in[14];
    const float* gs  = (const float*)d_in[15];
    const float* bes = (const float*)d_in[16];
    const float* Dw1 = (const float*)d_in[17];
    const float* Db1 = (const float*)d_in[18];
    const float* Dw2 = (const float*)d_in[19];
    const float* Db2 = (const float*)d_in[20];
    float* out = (float*)d_out;

    float* fsc; int* isc; double* sums;
    cudaGetSymbolAddress((void**)&fsc, g_fsc);
    cudaGetSymbolAddress((void**)&isc, g_isc);
    cudaGetSymbolAddress((void**)&sums, g_sums);

    float* HS  = fsc + 0 * BUF;
    float* SB1 = fsc + 1 * BUF;
    float* SB2 = fsc + 2 * BUF;
    float* SB3 = fsc + 3 * BUF;
    float* Z   = fsc + 4 * BUF;
    float* DIS = fsc + 5 * BUF;
    int* CNT = isc;
    int* OFF = CNT + N_NODES;
    int* CUR = OFF + N_NODES + 1;
    int* CSR = CUR + N_NODES;

    const int APRED_SMEM = 4 * 128 * TPITCH * 2;   // 73728 bytes
    cudaFuncSetAttribute(apred_mma_kernel, cudaFuncAttributeMaxDynamicSharedMemorySize, APRED_SMEM);

    // graph prep
    zero_all_kernel<<<47, 256>>>(CNT, sums);
    hist_kernel<<<1500, 256>>>(dst, CNT);
    scan_kernel<<<1, 1024>>>(CNT, OFF, CUR, DIS);
    fill_kernel<<<1500, 256>>>(src, dst, CUR, CSR);

    // layer 1: x(128) -> SB1  (stats for BN1 fused into gather)
    gcn_gemm_kernel<FIN_, false><<<750, 256>>>(x, W0, DIS, sums, nullptr, nullptr, HS);
    gather_sig_stats_kernel<<<1500, 256>>>(HS, DIS, OFF, CSR, b0, SB1, sums);

    // layer 2 (mean): BN1 folded into gemm
    gcn_gemm_kernel<DD, true><<<750, 256>>>(SB1, Wm, DIS, sums, g0, be0, HS);
    gather_sig_stats_kernel<<<1500, 256>>>(HS, DIS, OFF, CSR, bm, SB2, sums + 128);

    // layer 3 (logstd): BN1 folded into gemm
    gcn_gemm_kernel<DD, true><<<750, 256>>>(SB1, Ws, DIS, sums, g0, be0, HS);
    gather_sig_stats_kernel<<<1500, 256>>>(HS, DIS, OFF, CSR, bs, SB3, sums + 256);

    // z = noise*exp(bn(SB3)) + bn(SB2)
    z_bn_kernel<<<3000, 256>>>(noise, SB2, SB3, sums, gm, bem, gs, bes, Z);

    // decoder (both layers fused) -> out[0 : 12000*128]
    decoder_kernel<<<750, 256>>>(Z, Dw1, Db1, Dw2, Db2, out);

    // A_pred -> out[12000*128 : ]  — full-grid HMMA (R4-proven)
    dim3 grid((N_NODES + 127) / 128, (N_NODES + 127) / 128);
    apred_mma_kernel<<<grid, 256, APRED_SMEM>>>(Z, out + (size_t)N_NODES * FIN_);
}